// round 5
// baseline (speedup 1.0000x reference)
#include <cuda_runtime.h>
#include <cuda_fp16.h>
#include <stdint.h>
#include <math.h>

#define DIMX     128
#define NCODE    512
#define MTILE    32
#define NTHREADS 512
#define EPSF     1e-6f

#define XSS  136   // xs row stride (halves)
#define CB1S 40    // GEMM1 cb k-slice row stride
#define CB2S 136   // GEMM2 cb chunk row stride
#define PSS  520   // P row stride

// half-offsets in dynamic smem
#define XS_H   0
#define XS_L   4352
#define CB1    8704       // 2 buffers x (h 20480 + l 20480) = 81920, ends 90624
#define CB1BUF 40960
#define CB1LO  20480
#define P16H   0          // overlays XS/CB1 head (disjoint in time)
#define P16L   16640      // ends 33280
#define CB2    33280      // 2 buffers x 8704 = 17408, ends 50688
#define CB2BUF 8704
#define QRED   50688      // 3 x 32 x 132 floats = 25344 halves, ends 76032
#define SCR    90624      // 2048 floats of reduction scratch
#define SMEM_HALVES (SCR + 4096)
#define SMEM_BYTES  (SMEM_HALVES * 2)

__device__ __half cbh_g[NCODE * DIMX];
__device__ __half cbl_g[NCODE * DIMX];

__device__ __forceinline__ void split2(float v, __half& h, __half& l) {
    h = __float2half_rn(v);
    l = __float2half_rn(v - __half2float(h));
}

__device__ __forceinline__ void mma16(float* d,
                                      uint32_t a0, uint32_t a1, uint32_t a2, uint32_t a3,
                                      uint32_t b0, uint32_t b1) {
    asm volatile(
        "mma.sync.aligned.m16n8k16.row.col.f32.f16.f16.f32 "
        "{%0,%1,%2,%3},{%4,%5,%6,%7},{%8,%9},{%0,%1,%2,%3};"
        : "+f"(d[0]), "+f"(d[1]), "+f"(d[2]), "+f"(d[3])
        : "r"(a0), "r"(a1), "r"(a2), "r"(a3), "r"(b0), "r"(b1));
}

__device__ __forceinline__ void ldsm_x4(uint32_t& r0, uint32_t& r1, uint32_t& r2, uint32_t& r3,
                                        uint32_t addr) {
    asm volatile("ldmatrix.sync.aligned.m8n8.x4.shared.b16 {%0,%1,%2,%3},[%4];"
                 : "=r"(r0), "=r"(r1), "=r"(r2), "=r"(r3) : "r"(addr));
}
__device__ __forceinline__ void ldsm_x4t(uint32_t& r0, uint32_t& r1, uint32_t& r2, uint32_t& r3,
                                         uint32_t addr) {
    asm volatile("ldmatrix.sync.aligned.m8n8.x4.trans.shared.b16 {%0,%1,%2,%3},[%4];"
                 : "=r"(r0), "=r"(r1), "=r"(r2), "=r"(r3) : "r"(addr));
}
__device__ __forceinline__ void cp16(uint32_t dst, const void* src) {
    asm volatile("cp.async.cg.shared.global [%0], [%1], 16;" :: "r"(dst), "l"(src));
}
__device__ __forceinline__ void cp_commit() {
    asm volatile("cp.async.commit_group;" ::: "memory");
}
template<int N>
__device__ __forceinline__ void cp_wait() {
    asm volatile("cp.async.wait_group %0;" :: "n"(N) : "memory");
}

__global__ void cb_split_kernel(const float* __restrict__ cb) {
    int i = (blockIdx.x * 256 + threadIdx.x) * 4;
    float4 v = *(const float4*)(cb + i);
    __half h0, l0, h1, l1, h2, l2, h3, l3;
    split2(v.x, h0, l0); split2(v.y, h1, l1);
    split2(v.z, h2, l2); split2(v.w, h3, l3);
    *(half2*)(cbh_g + i)     = __halves2half2(h0, h1);
    *(half2*)(cbh_g + i + 2) = __halves2half2(h2, h3);
    *(half2*)(cbl_g + i)     = __halves2half2(l0, l1);
    *(half2*)(cbl_g + i + 2) = __halves2half2(l2, l3);
}

__global__ __launch_bounds__(NTHREADS, 1)
void gvq_main(const float* __restrict__ x,
              const float* __restrict__ mask,
              const float* __restrict__ noise,
              float* __restrict__ q_out,
              float* __restrict__ enc_out,
              float* __restrict__ idx_out)
{
    extern __shared__ __half sm[];
    __half* xs_h = sm + XS_H;
    __half* xs_l = sm + XS_L;
    __half* p16h = sm + P16H;
    __half* p16l = sm + P16L;
    float*  scrf = (float*)(sm + SCR);
    float* redD = scrf;
    float* redI = scrf + 512;
    float* redM = scrf + 1024;
    float* redS = scrf + 1536;

    const int tid  = threadIdx.x;
    const int wid  = tid >> 5;
    const int lane = tid & 31;
    const int lq   = lane >> 2;
    const int lr   = lane & 3;
    const int row0 = blockIdx.x * MTILE;
    const int wk   = wid >> 2;   // GEMM2: k quarter (128 codes)
    const int wn   = wid & 3;    // GEMM2: n32 group

    const uint32_t smem_u32 = (uint32_t)__cvta_generic_to_shared(sm);

    auto stage1 = [&](int kk, int buf) {
        uint32_t dstH = smem_u32 + (CB1 + buf * CB1BUF) * 2;
        uint32_t dstL = dstH + CB1LO * 2;
        #pragma unroll
        for (int j = 0; j < 4; j++) {
            int f = tid + 512 * j;           // 2048 cp16
            int r = f >> 2, q = f & 3;
            cp16(dstH + (r * CB1S + q * 8) * 2, cbh_g + r * DIMX + kk * 32 + q * 8);
        }
        #pragma unroll
        for (int j = 0; j < 4; j++) {
            int f = tid + 512 * j;
            int r = f >> 2, q = f & 3;
            cp16(dstL + (r * CB1S + q * 8) * 2, cbl_g + r * DIMX + kk * 32 + q * 8);
        }
        cp_commit();
    };
    auto stage2 = [&](int c, int buf) {
        uint32_t dst = smem_u32 + (CB2 + buf * CB2BUF) * 2;
        #pragma unroll
        for (int j = 0; j < 2; j++) {
            int f = tid + 512 * j;           // 1024 cp16
            int r = f >> 4, q = f & 15;
            int gc = (r >> 4) * 128 + c * 16 + (r & 15);
            cp16(dst + (r * CB2S + q * 8) * 2, cbh_g + gc * DIMX + q * 8);
        }
        cp_commit();
    };

    // prefetch GEMM1 slices 0 and 1 into both buffers
    stage1(0, 0);
    stage1(1, 1);

    // ================= Phase A: load x, nudge, normalize, split =================
    {
        int arow = tid >> 4;
        int u    = tid & 15;
        float mv = mask[row0 + arow];
        float nudge = (1.0f - mv) * EPSF;
        const float4* xp = (const float4*)(x + (size_t)(row0 + arow) * DIMX + u * 8);
        float4 t0 = xp[0], t1 = xp[1];
        float v[8] = { t0.x + nudge, t0.y + nudge, t0.z + nudge, t0.w + nudge,
                       t1.x + nudge, t1.y + nudge, t1.z + nudge, t1.w + nudge };
        float acc = 0.0f;
        #pragma unroll
        for (int j = 0; j < 8; j++) acc += v[j] * v[j];
        acc += __shfl_xor_sync(0xffffffffu, acc, 1);
        acc += __shfl_xor_sync(0xffffffffu, acc, 2);
        acc += __shfl_xor_sync(0xffffffffu, acc, 4);
        acc += __shfl_xor_sync(0xffffffffu, acc, 8);
        float nr = fmaxf(sqrtf(acc), EPSF);
        #pragma unroll
        for (int j = 0; j < 4; j++) {
            float a0 = v[2*j]   / nr;
            float a1 = v[2*j+1] / nr;
            __half h0, l0, h1, l1;
            split2(a0, h0, l0);
            split2(a1, h1, l1);
            *(half2*)&xs_h[arow * XSS + u * 8 + 2*j] = __halves2half2(h0, h1);
            *(half2*)&xs_l[arow * XSS + u * 8 + 2*j] = __halves2half2(l0, l1);
        }
    }

    // ================= GEMM1: scores = Xn @ CB^T (warp tile m32 x n32, 3-mma) =================
    float s[2][4][4];
    #pragma unroll
    for (int mf = 0; mf < 2; mf++)
        #pragma unroll
        for (int nf = 0; nf < 4; nf++)
            #pragma unroll
            for (int e = 0; e < 4; e++)
                s[mf][nf][e] = 0.0f;

    const uint32_t a1h = smem_u32 + (XS_H + (lane & 15) * XSS + (lane >> 4) * 8) * 2;
    const uint32_t a1l = a1h + (XS_L - XS_H) * 2;
    const uint32_t b1off = ((wid * 32 + (lane & 7) + ((lane >> 4) & 1) * 8) * CB1S
                          + ((lane >> 3) & 1) * 8) * 2;

    for (int kk = 0; kk < 4; kk++) {
        if (kk < 3) cp_wait<1>(); else cp_wait<0>();
        __syncthreads();
        uint32_t cb = smem_u32 + (CB1 + (kk & 1) * CB1BUF) * 2 + b1off;
        #pragma unroll
        for (int k16 = 0; k16 < 2; k16++) {
            uint32_t acol = (uint32_t)(kk * 32 + k16 * 16) * 2;
            uint32_t ah[8], al[8];
            ldsm_x4(ah[0], ah[1], ah[2], ah[3], a1h + acol);
            ldsm_x4(ah[4], ah[5], ah[6], ah[7], a1h + acol + 16 * XSS * 2);
            ldsm_x4(al[0], al[1], al[2], al[3], a1l + acol);
            ldsm_x4(al[4], al[5], al[6], al[7], a1l + acol + 16 * XSS * 2);
            #pragma unroll
            for (int g = 0; g < 2; g++) {
                uint32_t ba = cb + g * (16 * CB1S * 2) + k16 * 32;
                uint32_t bh0, bh1, bh2, bh3, bl0, bl1, bl2, bl3;
                ldsm_x4(bh0, bh1, bh2, bh3, ba);
                ldsm_x4(bl0, bl1, bl2, bl3, ba + CB1LO * 2);
                #pragma unroll
                for (int mf = 0; mf < 2; mf++) {
                    float* d0 = s[mf][g * 2 + 0];
                    float* d1 = s[mf][g * 2 + 1];
                    mma16(d0, ah[mf*4+0], ah[mf*4+1], ah[mf*4+2], ah[mf*4+3], bh0, bh1);
                    mma16(d0, ah[mf*4+0], ah[mf*4+1], ah[mf*4+2], ah[mf*4+3], bl0, bl1);
                    mma16(d0, al[mf*4+0], al[mf*4+1], al[mf*4+2], al[mf*4+3], bh0, bh1);
                    mma16(d1, ah[mf*4+0], ah[mf*4+1], ah[mf*4+2], ah[mf*4+3], bh2, bh3);
                    mma16(d1, ah[mf*4+0], ah[mf*4+1], ah[mf*4+2], ah[mf*4+3], bl2, bl3);
                    mma16(d1, al[mf*4+0], al[mf*4+1], al[mf*4+2], al[mf*4+3], bh2, bh3);
                }
            }
        }
        __syncthreads();
        if (kk < 2) stage1(kk + 2, kk & 1);
    }

    // prefetch GEMM2 chunks 0,1 (CB1/XS regions are now dead)
    stage2(0, 0);
    stage2(1, 1);

    // ================= Phase C: distances -> argmin -> gumbel softmax =================
    float mind[4], maxl[4], sums[4], invs[4];
    int   mini[4];
    #pragma unroll
    for (int rs = 0; rs < 4; rs++) {
        mind[rs] = 3.402823466e+38f;
        mini[rs] = 0;
        maxl[rs] = -3.402823466e+38f;
    }

    #pragma unroll
    for (int mf = 0; mf < 2; mf++) {
        #pragma unroll
        for (int eh = 0; eh < 2; eh++) {
            int rs = mf * 2 + eh;
            int grow = row0 + mf * 16 + eh * 8 + lq;
            const float* np = noise + (size_t)grow * NCODE + wid * 32 + 2 * lr;
            #pragma unroll
            for (int nf = 0; nf < 4; nf++) {
                float2 nz = *(const float2*)(np + nf * 8);
                float d0 = (1.0f - 2.0f * s[mf][nf][eh * 2])     + 1.0f;
                float d1 = (1.0f - 2.0f * s[mf][nf][eh * 2 + 1]) + 1.0f;
                int c0 = wid * 32 + nf * 8 + 2 * lr;
                if (d0 < mind[rs]) { mind[rs] = d0; mini[rs] = c0; }
                if (d1 < mind[rs]) { mind[rs] = d1; mini[rs] = c0 + 1; }
                float l0 = nz.x - d0;
                float l1 = nz.y - d1;
                maxl[rs] = fmaxf(maxl[rs], fmaxf(l0, l1));
                s[mf][nf][eh * 2]     = l0;
                s[mf][nf][eh * 2 + 1] = l1;
            }
        }
    }
    #pragma unroll
    for (int rs = 0; rs < 4; rs++) {
        #pragma unroll
        for (int off = 1; off < 4; off <<= 1) {
            float od = __shfl_xor_sync(0xffffffffu, mind[rs], off);
            int   oi = __shfl_xor_sync(0xffffffffu, mini[rs], off);
            if (od < mind[rs] || (od == mind[rs] && oi < mini[rs])) { mind[rs] = od; mini[rs] = oi; }
            maxl[rs] = fmaxf(maxl[rs], __shfl_xor_sync(0xffffffffu, maxl[rs], off));
        }
    }
    if (lr == 0) {
        #pragma unroll
        for (int rs = 0; rs < 4; rs++) {
            int row = (rs >> 1) * 16 + (rs & 1) * 8 + lq;
            redD[row * 16 + wid] = mind[rs];
            redI[row * 16 + wid] = (float)mini[rs];
            redM[row * 16 + wid] = maxl[rs];
        }
    }
    __syncthreads();
    #pragma unroll
    for (int rs = 0; rs < 4; rs++) {
        int row = (rs >> 1) * 16 + (rs & 1) * 8 + lq;
        float gd = redD[row * 16 + 0];
        int   gi = (int)redI[row * 16 + 0];
        float gm = redM[row * 16 + 0];
        #pragma unroll
        for (int w = 1; w < 16; w++) {
            float od = redD[row * 16 + w];
            int   oi = (int)redI[row * 16 + w];
            if (od < gd || (od == gd && oi < gi)) { gd = od; gi = oi; }
            gm = fmaxf(gm, redM[row * 16 + w]);
        }
        mini[rs] = gi;
        maxl[rs] = gm;
        sums[rs] = 0.0f;
    }
    #pragma unroll
    for (int mf = 0; mf < 2; mf++)
        #pragma unroll
        for (int eh = 0; eh < 2; eh++) {
            int rs = mf * 2 + eh;
            #pragma unroll
            for (int nf = 0; nf < 4; nf++) {
                float e0 = __expf(s[mf][nf][eh * 2]     - maxl[rs]);
                float e1 = __expf(s[mf][nf][eh * 2 + 1] - maxl[rs]);
                s[mf][nf][eh * 2]     = e0;
                s[mf][nf][eh * 2 + 1] = e1;
                sums[rs] += e0 + e1;
            }
        }
    #pragma unroll
    for (int rs = 0; rs < 4; rs++) {
        sums[rs] += __shfl_xor_sync(0xffffffffu, sums[rs], 1);
        sums[rs] += __shfl_xor_sync(0xffffffffu, sums[rs], 2);
    }
    if (lr == 0) {
        #pragma unroll
        for (int rs = 0; rs < 4; rs++) {
            int row = (rs >> 1) * 16 + (rs & 1) * 8 + lq;
            redS[row * 16 + wid] = sums[rs];
        }
    }
    __syncthreads();
    #pragma unroll
    for (int rs = 0; rs < 4; rs++) {
        int row = (rs >> 1) * 16 + (rs & 1) * 8 + lq;
        float t = 0.0f;
        #pragma unroll
        for (int w = 0; w < 16; w++) t += redS[row * 16 + w];
        invs[rs] = 1.0f / t;
    }

    // probs -> p16 smem + enc_out; indices
    #pragma unroll
    for (int mf = 0; mf < 2; mf++)
        #pragma unroll
        for (int eh = 0; eh < 2; eh++) {
            int rs = mf * 2 + eh;
            int row = mf * 16 + eh * 8 + lq;
            float* ep = enc_out + (size_t)(row0 + row) * NCODE + wid * 32 + 2 * lr;
            #pragma unroll
            for (int nf = 0; nf < 4; nf++) {
                float p0 = s[mf][nf][eh * 2]     * invs[rs];
                float p1 = s[mf][nf][eh * 2 + 1] * invs[rs];
                __half h0, l0, h1, l1;
                split2(p0, h0, l0);
                split2(p1, h1, l1);
                int col = wid * 32 + nf * 8 + 2 * lr;
                *(half2*)&p16h[row * PSS + col] = __halves2half2(h0, h1);
                *(half2*)&p16l[row * PSS + col] = __halves2half2(l0, l1);
                *(float2*)(ep + nf * 8) = make_float2(p0, p1);
            }
        }
    if (wid == 0 && lr == 0) {
        #pragma unroll
        for (int rs = 0; rs < 4; rs++) {
            int row = (rs >> 1) * 16 + (rs & 1) * 8 + lq;
            idx_out[row0 + row] = (float)mini[rs];
        }
    }
    __syncthreads();

    // ================= GEMM2: Q = P @ CB (split-k-4, warp tile m32 x n32, 2-mma) =================
    float q[2][4][4];
    #pragma unroll
    for (int mf = 0; mf < 2; mf++)
        #pragma unroll
        for (int nf = 0; nf < 4; nf++)
            #pragma unroll
            for (int e = 0; e < 4; e++)
                q[mf][nf][e] = 0.0f;

    const uint32_t a2h = smem_u32 + (P16H + (lane & 15) * PSS + (lane >> 4) * 8) * 2;
    const uint32_t a2l = a2h + (P16L - P16H) * 2;
    const uint32_t b2off = ((wk * 16 + (lane & 15)) * CB2S + wn * 32 + (lane >> 4) * 8) * 2;

    for (int c = 0; c < 8; c++) {
        if (c < 7) cp_wait<1>(); else cp_wait<0>();
        __syncthreads();
        uint32_t bbuf = smem_u32 + (CB2 + (c & 1) * CB2BUF) * 2 + b2off;
        uint32_t acol = (uint32_t)(wk * 128 + c * 16) * 2;
        uint32_t ah[8], al[8];
        ldsm_x4(ah[0], ah[1], ah[2], ah[3], a2h + acol);
        ldsm_x4(ah[4], ah[5], ah[6], ah[7], a2h + acol + 16 * PSS * 2);
        ldsm_x4(al[0], al[1], al[2], al[3], a2l + acol);
        ldsm_x4(al[4], al[5], al[6], al[7], a2l + acol + 16 * PSS * 2);
        #pragma unroll
        for (int g = 0; g < 2; g++) {
            uint32_t bh0, bh1, bh2, bh3;
            ldsm_x4t(bh0, bh1, bh2, bh3, bbuf + g * 32);
            #pragma unroll
            for (int mf = 0; mf < 2; mf++) {
                float* d0 = q[mf][g * 2 + 0];
                float* d1 = q[mf][g * 2 + 1];
                mma16(d0, ah[mf*4+0], ah[mf*4+1], ah[mf*4+2], ah[mf*4+3], bh0, bh1);
                mma16(d0, al[mf*4+0], al[mf*4+1], al[mf*4+2], al[mf*4+3], bh0, bh1);
                mma16(d1, ah[mf*4+0], ah[mf*4+1], ah[mf*4+2], ah[mf*4+3], bh2, bh3);
                mma16(d1, al[mf*4+0], al[mf*4+1], al[mf*4+2], al[mf*4+3], bh2, bh3);
            }
        }
        __syncthreads();
        if (c < 6) stage2(c + 2, c & 1);
    }

    // split-k reduction over 4 k-groups
    float* qredf = (float*)(sm + QRED);
    if (wk > 0) {
        #pragma unroll
        for (int mf = 0; mf < 2; mf++)
            #pragma unroll
            for (int nf = 0; nf < 4; nf++)
                #pragma unroll
                for (int e = 0; e < 4; e++) {
                    int row = mf * 16 + lq + (e >> 1) * 8;
                    int col = wn * 32 + nf * 8 + 2 * lr + (e & 1);
                    qredf[(wk - 1) * 4224 + row * 132 + col] = q[mf][nf][e];
                }
    }
    __syncthreads();
    if (wk == 0) {
        #pragma unroll
        for (int mf = 0; mf < 2; mf++)
            #pragma unroll
            for (int nf = 0; nf < 4; nf++)
                #pragma unroll
                for (int eh = 0; eh < 2; eh++) {
                    int row  = mf * 16 + lq + eh * 8;
                    int col0 = wn * 32 + nf * 8 + 2 * lr;
                    float v0 = q[mf][nf][eh * 2];
                    float v1 = q[mf][nf][eh * 2 + 1];
                    #pragma unroll
                    for (int p = 0; p < 3; p++) {
                        v0 += qredf[p * 4224 + row * 132 + col0];
                        v1 += qredf[p * 4224 + row * 132 + col0 + 1];
                    }
                    *(float2*)(q_out + (size_t)(row0 + row) * DIMX + col0)
                        = make_float2(v0, v1);
                }
    }
}

extern "C" void kernel_launch(void* const* d_in, const int* in_sizes, int n_in,
                              void* d_out, int out_size)
{
    const float* x        = (const float*)d_in[0];
    const float* mask     = (const float*)d_in[1];
    const float* codebook = (const float*)d_in[2];
    const float* noise    = (const float*)d_in[3];

    const int n = in_sizes[0] / DIMX;   // 131072

    float* q_out   = (float*)d_out;
    float* enc_out = q_out + (size_t)n * DIMX;
    float* idx_out = enc_out + (size_t)n * NCODE;

    cb_split_kernel<<<NCODE * DIMX / 1024, 256>>>(codebook);

    cudaFuncSetAttribute(gvq_main,
                         cudaFuncAttributeMaxDynamicSharedMemorySize,
                         SMEM_BYTES);
    gvq_main<<<n / MTILE, NTHREADS, SMEM_BYTES>>>(
        x, mask, noise, q_out, enc_out, idx_out);
}

// round 6
// speedup vs baseline: 1.2300x; 1.2300x over previous
#include <cuda_runtime.h>
#include <cuda_fp16.h>
#include <stdint.h>
#include <math.h>

#define DIMX     128
#define NCODE    512
#define MTILE    32
#define NTHREADS 256
#define EPSF     1e-6f

#define XSS  136   // xs row stride (halves)
#define CB2S 136   // GEMM2 cb chunk row stride
#define PSS  520   // P row stride

// half-offsets in dynamic smem
#define XS_H   0
#define XS_L   4352
#define CB1    8704       // 2 buffers x (h 8192 + l 8192) = 32768, ends 41472
#define CB1BUF 16384
#define CB1LO  8192
#define P16H   0          // overlays XS + CB1 head (disjoint in time)
#define P16L   16640      // ends 33280
#define CB2    33280      // 2 buffers x 8704 = 17408, ends 50688
#define CB2BUF 8704
#define SCR    50688      // 1024 floats of reduction scratch
#define SMEM_HALVES (SCR + 2048)
#define SMEM_BYTES  (SMEM_HALVES * 2)

__device__ __half cbh_g[NCODE * DIMX];
__device__ __half cbl_g[NCODE * DIMX];

__device__ __forceinline__ void split2(float v, __half& h, __half& l) {
    h = __float2half_rn(v);
    l = __float2half_rn(v - __half2float(h));
}

__device__ __forceinline__ void mma16(float* d,
                                      uint32_t a0, uint32_t a1, uint32_t a2, uint32_t a3,
                                      uint32_t b0, uint32_t b1) {
    asm volatile(
        "mma.sync.aligned.m16n8k16.row.col.f32.f16.f16.f32 "
        "{%0,%1,%2,%3},{%4,%5,%6,%7},{%8,%9},{%0,%1,%2,%3};"
        : "+f"(d[0]), "+f"(d[1]), "+f"(d[2]), "+f"(d[3])
        : "r"(a0), "r"(a1), "r"(a2), "r"(a3), "r"(b0), "r"(b1));
}

__device__ __forceinline__ void ldsm_x4(uint32_t& r0, uint32_t& r1, uint32_t& r2, uint32_t& r3,
                                        uint32_t addr) {
    asm volatile("ldmatrix.sync.aligned.m8n8.x4.shared.b16 {%0,%1,%2,%3},[%4];"
                 : "=r"(r0), "=r"(r1), "=r"(r2), "=r"(r3) : "r"(addr));
}
__device__ __forceinline__ void ldsm_x4t(uint32_t& r0, uint32_t& r1, uint32_t& r2, uint32_t& r3,
                                         uint32_t addr) {
    asm volatile("ldmatrix.sync.aligned.m8n8.x4.trans.shared.b16 {%0,%1,%2,%3},[%4];"
                 : "=r"(r0), "=r"(r1), "=r"(r2), "=r"(r3) : "r"(addr));
}
__device__ __forceinline__ void cp16(uint32_t dst, const void* src) {
    asm volatile("cp.async.cg.shared.global [%0], [%1], 16;" :: "r"(dst), "l"(src));
}
__device__ __forceinline__ void cp_commit() {
    asm volatile("cp.async.commit_group;" ::: "memory");
}
template<int N>
__device__ __forceinline__ void cp_wait() {
    asm volatile("cp.async.wait_group %0;" :: "n"(N) : "memory");
}

__global__ void cb_split_kernel(const float* __restrict__ cb) {
    int i = (blockIdx.x * 256 + threadIdx.x) * 4;
    float4 v = *(const float4*)(cb + i);
    __half h0, l0, h1, l1, h2, l2, h3, l3;
    split2(v.x, h0, l0); split2(v.y, h1, l1);
    split2(v.z, h2, l2); split2(v.w, h3, l3);
    *(half2*)(cbh_g + i)     = __halves2half2(h0, h1);
    *(half2*)(cbh_g + i + 2) = __halves2half2(h2, h3);
    *(half2*)(cbl_g + i)     = __halves2half2(l0, l1);
    *(half2*)(cbl_g + i + 2) = __halves2half2(l2, l3);
}

__global__ __launch_bounds__(NTHREADS, 2)
void gvq_main(const float* __restrict__ x,
              const float* __restrict__ mask,
              const float* __restrict__ noise,
              float* __restrict__ q_out,
              float* __restrict__ enc_out,
              float* __restrict__ idx_out)
{
    extern __shared__ __half sm[];
    __half* xs_h = sm + XS_H;
    __half* xs_l = sm + XS_L;
    __half* p16h = sm + P16H;
    __half* p16l = sm + P16L;
    float*  scrf = (float*)(sm + SCR);
    float* redD = scrf;
    float* redI = scrf + 256;
    float* redM = scrf + 512;
    float* redS = scrf + 768;

    const int tid  = threadIdx.x;
    const int wid  = tid >> 5;
    const int lane = tid & 31;
    const int lq   = lane >> 2;
    const int lr   = lane & 3;
    const int row0 = blockIdx.x * MTILE;
    const int wk   = wid >> 2;   // GEMM2: k-half
    const int wn   = wid & 3;    // GEMM2: n32 group

    const uint32_t smem_u32 = (uint32_t)__cvta_generic_to_shared(sm);

    // stage one k16-slice of all 512 codes (h + l), swizzled stride-16 layout
    auto stage1 = [&](int kk, int buf) {
        uint32_t dstH = smem_u32 + (CB1 + buf * CB1BUF) * 2;
        uint32_t dstL = dstH + CB1LO * 2;
        #pragma unroll
        for (int j = 0; j < 4; j++) {
            int f = tid + 256 * j;          // 1024 granule pairs
            int c = f >> 1, q = f & 1;
            uint32_t off = (uint32_t)c * 32 + q * 16;
            off ^= (off >> 3) & 0x10;       // conflict-free swizzle
            cp16(dstH + off, cbh_g + c * DIMX + kk * 16 + q * 8);
            cp16(dstL + off, cbl_g + c * DIMX + kk * 16 + q * 8);
        }
        cp_commit();
    };
    // stage one GEMM2 chunk: 2 k-groups x 32 codes, hi only
    auto stage2 = [&](int c, int buf) {
        uint32_t dst = smem_u32 + (CB2 + buf * CB2BUF) * 2;
        #pragma unroll
        for (int j = 0; j < 4; j++) {
            int f = tid + 256 * j;          // 1024 granules
            int r = f >> 4, q = f & 15;
            int gc = (r >> 5) * 256 + c * 32 + (r & 31);
            cp16(dst + (r * CB2S + q * 8) * 2, cbh_g + gc * DIMX + q * 8);
        }
        cp_commit();
    };

    stage1(0, 0);
    stage1(1, 1);

    // ================= Phase A: load x, nudge, normalize, split =================
    {
        int arow = wid * 4 + (lane >> 3);
        int u    = lane & 7;
        float mv = mask[row0 + arow];
        float nudge = (1.0f - mv) * EPSF;
        const float4* xp = (const float4*)(x + (size_t)(row0 + arow) * DIMX + u * 16);
        float v[16];
        float acc = 0.0f;
        #pragma unroll
        for (int j = 0; j < 4; j++) {
            float4 t = xp[j];
            v[4*j+0] = t.x + nudge; v[4*j+1] = t.y + nudge;
            v[4*j+2] = t.z + nudge; v[4*j+3] = t.w + nudge;
        }
        #pragma unroll
        for (int j = 0; j < 16; j++) acc += v[j] * v[j];
        acc += __shfl_xor_sync(0xffffffffu, acc, 1);
        acc += __shfl_xor_sync(0xffffffffu, acc, 2);
        acc += __shfl_xor_sync(0xffffffffu, acc, 4);
        float nr = fmaxf(sqrtf(acc), EPSF);
        #pragma unroll
        for (int j = 0; j < 8; j++) {
            float a0 = v[2*j]   / nr;
            float a1 = v[2*j+1] / nr;
            __half h0, l0, h1, l1;
            split2(a0, h0, l0);
            split2(a1, h1, l1);
            *(half2*)&xs_h[arow * XSS + u * 16 + 2*j] = __halves2half2(h0, h1);
            *(half2*)&xs_l[arow * XSS + u * 16 + 2*j] = __halves2half2(l0, l1);
        }
    }

    // ================= GEMM1: scores = Xn @ CB^T (warp m32 x n64, 3-mma) =================
    float s[2][8][4];
    #pragma unroll
    for (int mf = 0; mf < 2; mf++)
        #pragma unroll
        for (int nf = 0; nf < 8; nf++)
            #pragma unroll
            for (int e = 0; e < 4; e++)
                s[mf][nf][e] = 0.0f;

    const uint32_t a1h = smem_u32 + (XS_H + (lane & 15) * XSS + (lane >> 4) * 8) * 2;
    const uint32_t a1l = a1h + (XS_L - XS_H) * 2;
    uint32_t b1off;
    {
        int bc = wid * 64 + ((lane >> 4) & 1) * 8 + (lane & 7);
        int bq = (lane >> 3) & 1;
        b1off = (uint32_t)bc * 32 + bq * 16;
        b1off ^= (b1off >> 3) & 0x10;
    }

    for (int ss = 0; ss < 8; ss++) {
        if (ss < 7) cp_wait<1>(); else cp_wait<0>();
        __syncthreads();
        uint32_t cbB = smem_u32 + (CB1 + (ss & 1) * CB1BUF) * 2;
        uint32_t acol = (uint32_t)(ss * 16) * 2;
        uint32_t ah[8], al[8];
        ldsm_x4(ah[0], ah[1], ah[2], ah[3], a1h + acol);
        ldsm_x4(ah[4], ah[5], ah[6], ah[7], a1h + acol + 16 * XSS * 2);
        ldsm_x4(al[0], al[1], al[2], al[3], a1l + acol);
        ldsm_x4(al[4], al[5], al[6], al[7], a1l + acol + 16 * XSS * 2);
        #pragma unroll
        for (int g = 0; g < 4; g++) {
            uint32_t ba = cbB + b1off + g * 512;   // +16 codes per step
            uint32_t bh0, bh1, bh2, bh3, bl0, bl1, bl2, bl3;
            ldsm_x4(bh0, bh1, bh2, bh3, ba);
            ldsm_x4(bl0, bl1, bl2, bl3, ba + CB1LO * 2);
            #pragma unroll
            for (int mf = 0; mf < 2; mf++) {
                float* d0 = s[mf][g * 2 + 0];
                float* d1 = s[mf][g * 2 + 1];
                mma16(d0, ah[mf*4+0], ah[mf*4+1], ah[mf*4+2], ah[mf*4+3], bh0, bh1);
                mma16(d0, ah[mf*4+0], ah[mf*4+1], ah[mf*4+2], ah[mf*4+3], bl0, bl1);
                mma16(d0, al[mf*4+0], al[mf*4+1], al[mf*4+2], al[mf*4+3], bh0, bh1);
                mma16(d1, ah[mf*4+0], ah[mf*4+1], ah[mf*4+2], ah[mf*4+3], bh2, bh3);
                mma16(d1, ah[mf*4+0], ah[mf*4+1], ah[mf*4+2], ah[mf*4+3], bl2, bl3);
                mma16(d1, al[mf*4+0], al[mf*4+1], al[mf*4+2], al[mf*4+3], bh2, bh3);
            }
        }
        __syncthreads();
        if (ss < 6) stage1(ss + 2, ss & 1);
    }

    // prefetch GEMM2 chunks 0,1 (overlaps Phase C)
    stage2(0, 0);
    stage2(1, 1);

    // ================= Phase C: distances -> argmin -> gumbel softmax =================
    float mind[4], maxl[4], sums[4], invs[4];
    int   mini[4];
    #pragma unroll
    for (int rs = 0; rs < 4; rs++) {
        mind[rs] = 3.402823466e+38f;
        mini[rs] = 0;
        maxl[rs] = -3.402823466e+38f;
    }

    #pragma unroll
    for (int mf = 0; mf < 2; mf++) {
        #pragma unroll
        for (int eh = 0; eh < 2; eh++) {
            int rs = mf * 2 + eh;
            int grow = row0 + mf * 16 + eh * 8 + lq;
            const float* np = noise + (size_t)grow * NCODE + wid * 64 + 2 * lr;
            #pragma unroll
            for (int nf = 0; nf < 8; nf++) {
                float2 nz = *(const float2*)(np + nf * 8);
                float d0 = (1.0f - 2.0f * s[mf][nf][eh * 2])     + 1.0f;
                float d1 = (1.0f - 2.0f * s[mf][nf][eh * 2 + 1]) + 1.0f;
                int c0 = wid * 64 + nf * 8 + 2 * lr;
                if (d0 < mind[rs]) { mind[rs] = d0; mini[rs] = c0; }
                if (d1 < mind[rs]) { mind[rs] = d1; mini[rs] = c0 + 1; }
                float l0 = nz.x - d0;
                float l1 = nz.y - d1;
                maxl[rs] = fmaxf(maxl[rs], fmaxf(l0, l1));
                s[mf][nf][eh * 2]     = l0;
                s[mf][nf][eh * 2 + 1] = l1;
            }
        }
    }
    #pragma unroll
    for (int rs = 0; rs < 4; rs++) {
        #pragma unroll
        for (int off = 1; off < 4; off <<= 1) {
            float od = __shfl_xor_sync(0xffffffffu, mind[rs], off);
            int   oi = __shfl_xor_sync(0xffffffffu, mini[rs], off);
            if (od < mind[rs] || (od == mind[rs] && oi < mini[rs])) { mind[rs] = od; mini[rs] = oi; }
            maxl[rs] = fmaxf(maxl[rs], __shfl_xor_sync(0xffffffffu, maxl[rs], off));
        }
    }
    if (lr == 0) {
        #pragma unroll
        for (int rs = 0; rs < 4; rs++) {
            int row = (rs >> 1) * 16 + (rs & 1) * 8 + lq;
            redD[row * 8 + wid] = mind[rs];
            redI[row * 8 + wid] = (float)mini[rs];
            redM[row * 8 + wid] = maxl[rs];
        }
    }
    __syncthreads();
    #pragma unroll
    for (int rs = 0; rs < 4; rs++) {
        int row = (rs >> 1) * 16 + (rs & 1) * 8 + lq;
        float gd = redD[row * 8 + 0];
        int   gi = (int)redI[row * 8 + 0];
        float gm = redM[row * 8 + 0];
        #pragma unroll
        for (int w = 1; w < 8; w++) {
            float od = redD[row * 8 + w];
            int   oi = (int)redI[row * 8 + w];
            if (od < gd || (od == gd && oi < gi)) { gd = od; gi = oi; }
            gm = fmaxf(gm, redM[row * 8 + w]);
        }
        mini[rs] = gi;
        maxl[rs] = gm;
        sums[rs] = 0.0f;
    }
    #pragma unroll
    for (int mf = 0; mf < 2; mf++)
        #pragma unroll
        for (int eh = 0; eh < 2; eh++) {
            int rs = mf * 2 + eh;
            #pragma unroll
            for (int nf = 0; nf < 8; nf++) {
                float e0 = __expf(s[mf][nf][eh * 2]     - maxl[rs]);
                float e1 = __expf(s[mf][nf][eh * 2 + 1] - maxl[rs]);
                s[mf][nf][eh * 2]     = e0;
                s[mf][nf][eh * 2 + 1] = e1;
                sums[rs] += e0 + e1;
            }
        }
    #pragma unroll
    for (int rs = 0; rs < 4; rs++) {
        sums[rs] += __shfl_xor_sync(0xffffffffu, sums[rs], 1);
        sums[rs] += __shfl_xor_sync(0xffffffffu, sums[rs], 2);
    }
    if (lr == 0) {
        #pragma unroll
        for (int rs = 0; rs < 4; rs++) {
            int row = (rs >> 1) * 16 + (rs & 1) * 8 + lq;
            redS[row * 8 + wid] = sums[rs];
        }
    }
    __syncthreads();
    #pragma unroll
    for (int rs = 0; rs < 4; rs++) {
        int row = (rs >> 1) * 16 + (rs & 1) * 8 + lq;
        float t = 0.0f;
        #pragma unroll
        for (int w = 0; w < 8; w++) t += redS[row * 8 + w];
        invs[rs] = 1.0f / t;
    }
    __syncthreads();   // xs/cb1 regions dead; safe to write p16

    // probs -> p16 smem + enc_out; indices
    #pragma unroll
    for (int mf = 0; mf < 2; mf++)
        #pragma unroll
        for (int eh = 0; eh < 2; eh++) {
            int rs = mf * 2 + eh;
            int row = mf * 16 + eh * 8 + lq;
            float* ep = enc_out + (size_t)(row0 + row) * NCODE + wid * 64 + 2 * lr;
            #pragma unroll
            for (int nf = 0; nf < 8; nf++) {
                float p0 = s[mf][nf][eh * 2]     * invs[rs];
                float p1 = s[mf][nf][eh * 2 + 1] * invs[rs];
                __half h0, l0, h1, l1;
                split2(p0, h0, l0);
                split2(p1, h1, l1);
                int col = wid * 64 + nf * 8 + 2 * lr;
                *(half2*)&p16h[row * PSS + col] = __halves2half2(h0, h1);
                *(half2*)&p16l[row * PSS + col] = __halves2half2(l0, l1);
                *(float2*)(ep + nf * 8) = make_float2(p0, p1);
            }
        }
    if (wid == 0 && lr == 0) {
        #pragma unroll
        for (int rs = 0; rs < 4; rs++) {
            int row = (rs >> 1) * 16 + (rs & 1) * 8 + lq;
            idx_out[row0 + row] = (float)mini[rs];
        }
    }
    __syncthreads();

    // ================= GEMM2: Q = P @ CB (split-k-2, warp m32 x n32, 2-mma) =================
    float q[2][4][4];
    #pragma unroll
    for (int mf = 0; mf < 2; mf++)
        #pragma unroll
        for (int nf = 0; nf < 4; nf++)
            #pragma unroll
            for (int e = 0; e < 4; e++)
                q[mf][nf][e] = 0.0f;

    const uint32_t a2h = smem_u32 + (P16H + (lane & 15) * PSS + (lane >> 4) * 8) * 2;
    const uint32_t a2l = a2h + (P16L - P16H) * 2;
    const uint32_t b2off = ((wk * 32 + (lane & 15)) * CB2S + wn * 32 + (lane >> 4) * 8) * 2;

    for (int c = 0; c < 8; c++) {
        if (c < 7) cp_wait<1>(); else cp_wait<0>();
        __syncthreads();
        uint32_t bbuf = smem_u32 + (CB2 + (c & 1) * CB2BUF) * 2 + b2off;
        #pragma unroll
        for (int k16 = 0; k16 < 2; k16++) {
            uint32_t acol = (uint32_t)(wk * 256 + c * 32 + k16 * 16) * 2;
            uint32_t ah[8], al[8];
            ldsm_x4(ah[0], ah[1], ah[2], ah[3], a2h + acol);
            ldsm_x4(ah[4], ah[5], ah[6], ah[7], a2h + acol + 16 * PSS * 2);
            ldsm_x4(al[0], al[1], al[2], al[3], a2l + acol);
            ldsm_x4(al[4], al[5], al[6], al[7], a2l + acol + 16 * PSS * 2);
            #pragma unroll
            for (int g = 0; g < 2; g++) {
                uint32_t bh0, bh1, bh2, bh3;
                ldsm_x4t(bh0, bh1, bh2, bh3, bbuf + k16 * (16 * CB2S * 2) + g * 32);
                #pragma unroll
                for (int mf = 0; mf < 2; mf++) {
                    float* d0 = q[mf][g * 2 + 0];
                    float* d1 = q[mf][g * 2 + 1];
                    mma16(d0, ah[mf*4+0], ah[mf*4+1], ah[mf*4+2], ah[mf*4+3], bh0, bh1);
                    mma16(d0, al[mf*4+0], al[mf*4+1], al[mf*4+2], al[mf*4+3], bh0, bh1);
                    mma16(d1, ah[mf*4+0], ah[mf*4+1], ah[mf*4+2], ah[mf*4+3], bh2, bh3);
                    mma16(d1, al[mf*4+0], al[mf*4+1], al[mf*4+2], al[mf*4+3], bh2, bh3);
                }
            }
        }
        __syncthreads();
        if (c < 6) stage2(c + 2, c & 1);
    }

    // split-k-2 reduction (qred aliases dead cb2 buffers)
    float* qred = (float*)(sm + CB2);
    if (wk == 1) {
        #pragma unroll
        for (int mf = 0; mf < 2; mf++)
            #pragma unroll
            for (int nf = 0; nf < 4; nf++)
                #pragma unroll
                for (int e = 0; e < 4; e++) {
                    int row = mf * 16 + lq + (e >> 1) * 8;
                    int col = wn * 32 + nf * 8 + 2 * lr + (e & 1);
                    qred[row * 132 + col] = q[mf][nf][e];
                }
    }
    __syncthreads();
    if (wk == 0) {
        #pragma unroll
        for (int mf = 0; mf < 2; mf++)
            #pragma unroll
            for (int nf = 0; nf < 4; nf++)
                #pragma unroll
                for (int eh = 0; eh < 2; eh++) {
                    int row  = mf * 16 + lq + eh * 8;
                    int col0 = wn * 32 + nf * 8 + 2 * lr;
                    float v0 = q[mf][nf][eh * 2]     + qred[row * 132 + col0];
                    float v1 = q[mf][nf][eh * 2 + 1] + qred[row * 132 + col0 + 1];
                    *(float2*)(q_out + (size_t)(row0 + row) * DIMX + col0)
                        = make_float2(v0, v1);
                }
    }
}

extern "C" void kernel_launch(void* const* d_in, const int* in_sizes, int n_in,
                              void* d_out, int out_size)
{
    const float* x        = (const float*)d_in[0];
    const float* mask     = (const float*)d_in[1];
    const float* codebook = (const float*)d_in[2];
    const float* noise    = (const float*)d_in[3];

    const int n = in_sizes[0] / DIMX;   // 131072

    float* q_out   = (float*)d_out;
    float* enc_out = q_out + (size_t)n * DIMX;
    float* idx_out = enc_out + (size_t)n * NCODE;

    cb_split_kernel<<<NCODE * DIMX / 1024, 256>>>(codebook);

    cudaFuncSetAttribute(gvq_main,
                         cudaFuncAttributeMaxDynamicSharedMemorySize,
                         SMEM_BYTES);
    gvq_main<<<n / MTILE, NTHREADS, SMEM_BYTES>>>(
        x, mask, noise, q_out, enc_out, idx_out);
}